// round 2
// baseline (speedup 1.0000x reference)
#include <cuda_runtime.h>
#include <mma.h>

using namespace nvcuda;

#define SEQ   2048
#define DIMSZ 4096
#define NHEAD 32
#define HDIM  128

// Scratch (device globals: allocation-free per harness rules)
__device__ float g_q[(size_t)SEQ * DIMSZ];
__device__ float g_k[(size_t)SEQ * DIMSZ];
__device__ float g_v[(size_t)SEQ * DIMSZ];
__device__ float g_o[(size_t)SEQ * DIMSZ];

__device__ __forceinline__ float to_tf32(float x) { return wmma::__float_to_tf32(x); }

// ---------------------------------------------------------------------------
// GEMM v2: C[2048,4096] = A[2048,4096] @ B[4096,4096], TF32 tensor cores.
// Block tile 128x128, BK=32. 256 threads = 8 warps, warp grid 4x2 (32x64).
// Double-buffered smem + register prefetch: one __syncthreads per k-iter.
// ---------------------------------------------------------------------------
#define GM 2048
#define GN 4096
#define GK 4096
#define BK 32
#define LDA 36    // 32 + 4 pad
#define LDB 132   // 128 + 4 pad
#define GEMM_SMEM_FLOATS (2 * 128 * LDA + 2 * BK * LDB)
#define GEMM_SMEM_BYTES  (GEMM_SMEM_FLOATS * 4)
#define NT (GK / BK)   // 128 k-tiles

__device__ __forceinline__ void gemm_core(const float* __restrict__ A,
                                          const float* __restrict__ B,
                                          float* __restrict__ C,
                                          float* sm)
{
    float* As = sm;                    // 2 x [128][LDA]
    float* Bs = sm + 2 * 128 * LDA;    // 2 x [BK][LDB]

    const int tid = threadIdx.x;
    const int w   = tid >> 5;
    const int bm  = blockIdx.x * 128;
    const int bn  = blockIdx.y * 128;
    const int wr  = (w >> 1) * 32;     // warp row in block tile
    const int wc  = (w & 1) * 64;      // warp col in block tile

    wmma::fragment<wmma::accumulator, 16, 16, 8, float> acc[2][4];
#pragma unroll
    for (int i = 0; i < 2; i++)
#pragma unroll
        for (int j = 0; j < 4; j++) wmma::fill_fragment(acc[i][j], 0.0f);

    // Per-thread load coords (4 float4 each for A and B per tile)
    // A tile 128x32: idx = tid + i*256 -> r=idx>>3, k4=(idx&7)<<2
    // B tile 32x128: idx = tid + i*256 -> r=idx>>5, c4=(idx&31)<<2

    // Prologue: tile 0 -> buffer 0
#pragma unroll
    for (int i = 0; i < 4; i++) {
        int idx = tid + i * 256;
        int r = idx >> 3, k4 = (idx & 7) << 2;
        float4 v = *reinterpret_cast<const float4*>(A + (size_t)(bm + r) * GK + k4);
        *reinterpret_cast<float4*>(&As[r * LDA + k4]) =
            make_float4(to_tf32(v.x), to_tf32(v.y), to_tf32(v.z), to_tf32(v.w));
    }
#pragma unroll
    for (int i = 0; i < 4; i++) {
        int idx = tid + i * 256;
        int r = idx >> 5, c4 = (idx & 31) << 2;
        float4 v = *reinterpret_cast<const float4*>(B + (size_t)r * GN + bn + c4);
        *reinterpret_cast<float4*>(&Bs[r * LDB + c4]) =
            make_float4(to_tf32(v.x), to_tf32(v.y), to_tf32(v.z), to_tf32(v.w));
    }
    __syncthreads();

    for (int t = 0; t < NT; t++) {
        float4 pa[4], pb[4];
        const bool has_next = (t + 1 < NT);
        if (has_next) {
            int kk = (t + 1) * BK;
#pragma unroll
            for (int i = 0; i < 4; i++) {
                int idx = tid + i * 256;
                int r = idx >> 3, k4 = (idx & 7) << 2;
                pa[i] = *reinterpret_cast<const float4*>(A + (size_t)(bm + r) * GK + kk + k4);
            }
#pragma unroll
            for (int i = 0; i < 4; i++) {
                int idx = tid + i * 256;
                int r = idx >> 5, c4 = (idx & 31) << 2;
                pb[i] = *reinterpret_cast<const float4*>(B + (size_t)(kk + r) * GN + bn + c4);
            }
        }

        const float* Ac = As + (t & 1) * 128 * LDA;
        const float* Bc = Bs + (t & 1) * BK * LDB;
#pragma unroll
        for (int ks = 0; ks < 4; ks++) {
            wmma::fragment<wmma::matrix_a, 16, 16, 8, wmma::precision::tf32, wmma::row_major> a[2];
            wmma::fragment<wmma::matrix_b, 16, 16, 8, wmma::precision::tf32, wmma::row_major> b[4];
#pragma unroll
            for (int i = 0; i < 2; i++)
                wmma::load_matrix_sync(a[i], &Ac[(wr + i * 16) * LDA + ks * 8], LDA);
#pragma unroll
            for (int j = 0; j < 4; j++)
                wmma::load_matrix_sync(b[j], &Bc[(ks * 8) * LDB + wc + j * 16], LDB);
#pragma unroll
            for (int i = 0; i < 2; i++)
#pragma unroll
                for (int j = 0; j < 4; j++)
                    wmma::mma_sync(acc[i][j], a[i], b[j], acc[i][j]);
        }

        if (has_next) {
            float* An = As + ((t + 1) & 1) * 128 * LDA;
            float* Bn = Bs + ((t + 1) & 1) * BK * LDB;
#pragma unroll
            for (int i = 0; i < 4; i++) {
                int idx = tid + i * 256;
                int r = idx >> 3, k4 = (idx & 7) << 2;
                *reinterpret_cast<float4*>(&An[r * LDA + k4]) =
                    make_float4(to_tf32(pa[i].x), to_tf32(pa[i].y), to_tf32(pa[i].z), to_tf32(pa[i].w));
            }
#pragma unroll
            for (int i = 0; i < 4; i++) {
                int idx = tid + i * 256;
                int r = idx >> 5, c4 = (idx & 31) << 2;
                *reinterpret_cast<float4*>(&Bn[r * LDB + c4]) =
                    make_float4(to_tf32(pb[i].x), to_tf32(pb[i].y), to_tf32(pb[i].z), to_tf32(pb[i].w));
            }
            __syncthreads();
        }
    }

#pragma unroll
    for (int i = 0; i < 2; i++)
#pragma unroll
        for (int j = 0; j < 4; j++)
            wmma::store_matrix_sync(C + (size_t)(bm + wr + i * 16) * GN + bn + wc + j * 16,
                                    acc[i][j], GN, wmma::mem_row_major);
}

__global__ __launch_bounds__(256) void gemm_qkv(const float* __restrict__ x,
                                                const float* __restrict__ wq,
                                                const float* __restrict__ wk,
                                                const float* __restrict__ wv)
{
    extern __shared__ float sm[];
    const float* B;
    float* C;
    if (blockIdx.z == 0)      { B = wq; C = g_q; }
    else if (blockIdx.z == 1) { B = wk; C = g_k; }
    else                      { B = wv; C = g_v; }
    gemm_core(x, B, C, sm);
}

__global__ __launch_bounds__(256) void gemm_out(const float* __restrict__ A,
                                                const float* __restrict__ B,
                                                float* __restrict__ C)
{
    extern __shared__ float sm[];
    gemm_core(A, B, C, sm);
}

// ---------------------------------------------------------------------------
// RoPE applied in-place to g_q and g_k.
// ---------------------------------------------------------------------------
__global__ void rope_kernel(const float* __restrict__ fcos, const float* __restrict__ fsin)
{
    int idx = blockIdx.x * blockDim.x + threadIdx.x;  // SEQ*NHEAD*64 pairs
    if (idx >= SEQ * NHEAD * (HDIM / 2)) return;
    int i = idx & 63;
    int h = (idx >> 6) & (NHEAD - 1);
    int s = idx >> 11;
    float c  = fcos[s * 64 + i];
    float sn = fsin[s * 64 + i];
    size_t off = (size_t)s * DIMSZ + h * HDIM + 2 * i;
    float q0 = g_q[off], q1 = g_q[off + 1];
    g_q[off]     = q0 * c - q1 * sn;
    g_q[off + 1] = q0 * sn + q1 * c;
    float k0 = g_k[off], k1 = g_k[off + 1];
    g_k[off]     = k0 * c - k1 * sn;
    g_k[off + 1] = k0 * sn + k1 * c;
}

// ---------------------------------------------------------------------------
// Flash attention: block = (q-block of 64 rows, head). Online softmax, causal.
// ---------------------------------------------------------------------------
#define LDQ 136   // 128 + 8 pad
#define LDS_S 72  // 64 + 8 pad
#define FLASH_SMEM_FLOATS (4 * 64 * LDQ + 64 * LDS_S + 3 * 64)
#define FLASH_SMEM_BYTES (FLASH_SMEM_FLOATS * 4)

__global__ __launch_bounds__(256) void flash_attn()
{
    extern __shared__ float sm[];
    float* Qs   = sm;                  // 64 x LDQ
    float* Ks   = Qs + 64 * LDQ;
    float* Vs   = Ks + 64 * LDQ;
    float* Os   = Vs + 64 * LDQ;
    float* Ss   = Os + 64 * LDQ;       // 64 x LDS_S
    float* mrow = Ss + 64 * LDS_S;
    float* lrow = mrow + 64;
    float* arow = lrow + 64;

    const int qb  = blockIdx.x;
    const int h   = blockIdx.y;
    const int tid = threadIdx.x;
    const int w   = tid >> 5;
    const float scale = 0.08838834764831845f;  // 1/sqrt(128)

    const float* Qg = g_q + (size_t)qb * 64 * DIMSZ + h * HDIM;
#pragma unroll
    for (int i = 0; i < 8; i++) {
        int idx = tid + i * 256;
        int r = idx >> 5, d4 = (idx & 31) << 2;
        float4 v = *reinterpret_cast<const float4*>(Qg + (size_t)r * DIMSZ + d4);
        *reinterpret_cast<float4*>(&Qs[r * LDQ + d4]) =
            make_float4(to_tf32(v.x), to_tf32(v.y), to_tf32(v.z), to_tf32(v.w));
    }
    for (int i = tid; i < 64 * LDQ; i += 256) Os[i] = 0.0f;
    if (tid < 64) { mrow[tid] = -1e30f; lrow[tid] = 0.0f; }
    __syncthreads();

    for (int kt = 0; kt <= qb; kt++) {
        const float* Kg = g_k + (size_t)kt * 64 * DIMSZ + h * HDIM;
        const float* Vg = g_v + (size_t)kt * 64 * DIMSZ + h * HDIM;
#pragma unroll
        for (int i = 0; i < 8; i++) {
            int idx = tid + i * 256;
            int r = idx >> 5, d4 = (idx & 31) << 2;
            float4 kv = *reinterpret_cast<const float4*>(Kg + (size_t)r * DIMSZ + d4);
            float4 vv = *reinterpret_cast<const float4*>(Vg + (size_t)r * DIMSZ + d4);
            *reinterpret_cast<float4*>(&Ks[r * LDQ + d4]) =
                make_float4(to_tf32(kv.x), to_tf32(kv.y), to_tf32(kv.z), to_tf32(kv.w));
            *reinterpret_cast<float4*>(&Vs[r * LDQ + d4]) =
                make_float4(to_tf32(vv.x), to_tf32(vv.y), to_tf32(vv.z), to_tf32(vv.w));
        }
        __syncthreads();

        // S = scale * Q @ K^T : warp grid 4x2, each warp 16x32
        {
            const int wr = (w >> 1) * 16;
            const int wc = (w & 1) * 32;
            wmma::fragment<wmma::accumulator, 16, 16, 8, float> c[2];
            wmma::fill_fragment(c[0], 0.0f);
            wmma::fill_fragment(c[1], 0.0f);
#pragma unroll
            for (int ks = 0; ks < 16; ks++) {
                wmma::fragment<wmma::matrix_a, 16, 16, 8, wmma::precision::tf32, wmma::row_major> a;
                wmma::load_matrix_sync(a, &Qs[wr * LDQ + ks * 8], LDQ);
#pragma unroll
                for (int j = 0; j < 2; j++) {
                    wmma::fragment<wmma::matrix_b, 16, 16, 8, wmma::precision::tf32, wmma::col_major> b;
                    wmma::load_matrix_sync(b, &Ks[(wc + j * 16) * LDQ + ks * 8], LDQ);
                    wmma::mma_sync(c[j], a, b, c[j]);
                }
            }
#pragma unroll
            for (int j = 0; j < 2; j++) {
#pragma unroll
                for (int t = 0; t < c[j].num_elements; t++) c[j].x[t] *= scale;
                wmma::store_matrix_sync(&Ss[wr * LDS_S + wc + j * 16], c[j], LDS_S,
                                        wmma::mem_row_major);
            }
        }
        __syncthreads();

        // Online softmax: 4 threads per row
        {
            int r   = tid >> 2;
            int sub = tid & 3;
            int smax = (kt == qb) ? (r + 1) : 64;
            float mloc = -1e30f;
            int c0 = sub * 16;
#pragma unroll
            for (int c = 0; c < 16; c++) {
                int cc = c0 + c;
                if (cc < smax) mloc = fmaxf(mloc, Ss[r * LDS_S + cc]);
            }
#pragma unroll
            for (int o = 1; o < 4; o <<= 1)
                mloc = fmaxf(mloc, __shfl_xor_sync(0xffffffffu, mloc, o));
            float mo = mrow[r];
            float mn = fmaxf(mo, mloc);
            float alpha = __expf(mo - mn);
            float lsum = 0.0f;
#pragma unroll
            for (int c = 0; c < 16; c++) {
                int cc = c0 + c;
                float p = (cc < smax) ? __expf(Ss[r * LDS_S + cc] - mn) : 0.0f;
                p = to_tf32(p);
                Ss[r * LDS_S + cc] = p;
                lsum += p;
            }
#pragma unroll
            for (int o = 1; o < 4; o <<= 1)
                lsum += __shfl_xor_sync(0xffffffffu, lsum, o);
            if (sub == 0) {
                lrow[r] = lrow[r] * alpha + lsum;
                mrow[r] = mn;
                arow[r] = alpha;
            }
        }
        __syncthreads();

        // Rescale O accumulator
        for (int i = tid; i < 64 * 128; i += 256) {
            int r = i >> 7, d = i & 127;
            Os[r * LDQ + d] *= arow[r];
        }
        __syncthreads();

        // O += P @ V : warp grid 2x4, each warp 32x32
        {
            const int wr = (w >> 2) * 32;
            const int wc = (w & 3) * 32;
            wmma::fragment<wmma::accumulator, 16, 16, 8, float> c[2][2];
#pragma unroll
            for (int i = 0; i < 2; i++)
#pragma unroll
                for (int j = 0; j < 2; j++)
                    wmma::load_matrix_sync(c[i][j], &Os[(wr + i * 16) * LDQ + wc + j * 16],
                                           LDQ, wmma::mem_row_major);
#pragma unroll
            for (int ks = 0; ks < 8; ks++) {
                wmma::fragment<wmma::matrix_a, 16, 16, 8, wmma::precision::tf32, wmma::row_major> a[2];
                wmma::fragment<wmma::matrix_b, 16, 16, 8, wmma::precision::tf32, wmma::row_major> b[2];
#pragma unroll
                for (int i = 0; i < 2; i++)
                    wmma::load_matrix_sync(a[i], &Ss[(wr + i * 16) * LDS_S + ks * 8], LDS_S);
#pragma unroll
                for (int j = 0; j < 2; j++)
                    wmma::load_matrix_sync(b[j], &Vs[(ks * 8) * LDQ + wc + j * 16], LDQ);
#pragma unroll
                for (int i = 0; i < 2; i++)
#pragma unroll
                    for (int j = 0; j < 2; j++)
                        wmma::mma_sync(c[i][j], a[i], b[j], c[i][j]);
            }
#pragma unroll
            for (int i = 0; i < 2; i++)
#pragma unroll
                for (int j = 0; j < 2; j++)
                    wmma::store_matrix_sync(&Os[(wr + i * 16) * LDQ + wc + j * 16],
                                            c[i][j], LDQ, wmma::mem_row_major);
        }
        __syncthreads();
    }

    float* Og = g_o + (size_t)qb * 64 * DIMSZ + h * HDIM;
    for (int i = tid; i < 64 * 128; i += 256) {
        int r = i >> 7, d = i & 127;
        Og[(size_t)r * DIMSZ + d] = Os[r * LDQ + d] / lrow[r];
    }
}

// ---------------------------------------------------------------------------
extern "C" void kernel_launch(void* const* d_in, const int* in_sizes, int n_in,
                              void* d_out, int out_size)
{
    const float* x  = (const float*)d_in[0];
    const float* wq = (const float*)d_in[1];
    const float* wk = (const float*)d_in[2];
    const float* wv = (const float*)d_in[3];
    const float* wo = (const float*)d_in[4];
    const float* fc = (const float*)d_in[5];
    const float* fs = (const float*)d_in[6];
    float* out = (float*)d_out;

    float* o;
    cudaGetSymbolAddress((void**)&o, g_o);

    cudaFuncSetAttribute(gemm_qkv, cudaFuncAttributeMaxDynamicSharedMemorySize,
                         GEMM_SMEM_BYTES);
    cudaFuncSetAttribute(gemm_out, cudaFuncAttributeMaxDynamicSharedMemorySize,
                         GEMM_SMEM_BYTES);
    cudaFuncSetAttribute(flash_attn, cudaFuncAttributeMaxDynamicSharedMemorySize,
                         FLASH_SMEM_BYTES);

    dim3 qkv_grid(GM / 128, GN / 128, 3);
    gemm_qkv<<<qkv_grid, 256, GEMM_SMEM_BYTES>>>(x, wq, wk, wv);

    int npairs = SEQ * NHEAD * (HDIM / 2);
    rope_kernel<<<(npairs + 255) / 256, 256>>>(fc, fs);

    flash_attn<<<dim3(SEQ / 64, NHEAD), 256, FLASH_SMEM_BYTES>>>();

    dim3 ogrid(GM / 128, GN / 128);
    gemm_out<<<ogrid, 256, GEMM_SMEM_BYTES>>>(o, wo, out);
}

// round 4
// speedup vs baseline: 1.2215x; 1.2215x over previous
#include <cuda_runtime.h>
#include <cstdint>
#include <mma.h>

using namespace nvcuda;

#define SEQ   2048
#define DIMSZ 4096
#define NHEAD 32
#define HDIM  128

// Scratch (device globals: allocation-free per harness rules)
__device__ float g_q[(size_t)SEQ * DIMSZ];
__device__ float g_k[(size_t)SEQ * DIMSZ];
__device__ float g_v[(size_t)SEQ * DIMSZ];
__device__ float g_o[(size_t)SEQ * DIMSZ];
__device__ float g_xt[(size_t)SEQ * DIMSZ];              // tf32-rounded x
__device__ float g_wt[(size_t)4 * DIMSZ * DIMSZ];        // tf32-rounded wq,wk,wv,wo

__device__ __forceinline__ float to_tf32(float x) { return wmma::__float_to_tf32(x); }

__device__ __forceinline__ void cp16(float* s, const float* g) {
    unsigned int sa = (unsigned int)__cvta_generic_to_shared(s);
    asm volatile("cp.async.cg.shared.global [%0], [%1], 16;" :: "r"(sa), "l"(g));
}
#define CP_COMMIT() asm volatile("cp.async.commit_group;")
#define CP_WAIT1()  asm volatile("cp.async.wait_group 1;")

// ---------------------------------------------------------------------------
// tf32 pre-round: out[i] = RN_tf32(in[i]) (vectorized)
// ---------------------------------------------------------------------------
__global__ void cvt_tf32_kernel(const float4* __restrict__ in, float4* __restrict__ out, int n4)
{
    int i = blockIdx.x * blockDim.x + threadIdx.x;
    if (i >= n4) return;
    float4 v = in[i];
    out[i] = make_float4(to_tf32(v.x), to_tf32(v.y), to_tf32(v.z), to_tf32(v.w));
}

// ---------------------------------------------------------------------------
// GEMM v3: C[2048,4096] = A[2048,4096] @ B[4096,4096], TF32 tensor cores.
// Block tile 128x128, BK=32, cp.async 3-stage pipeline. 256 thr = 8 warps,
// warp grid 4x2 (32x64 each). A,B must be pre-rounded to tf32.
// ---------------------------------------------------------------------------
#define GM 2048
#define GN 4096
#define GK 4096
#define BK 32
#define NT (GK / BK)    // 128
#define STAGES 3
#define LDA 36          // 144B rows: 16B-multiple -> cp.async ok, pad kills conflicts
#define LDB 132         // 528B rows: 16B-multiple
#define ASTAGE (128 * LDA)
#define BSTAGE (BK * LDB)
#define GEMM_SMEM_BYTES (STAGES * (ASTAGE + BSTAGE) * 4)

__device__ __forceinline__ void issue_stage(const float* __restrict__ A,
                                            const float* __restrict__ B,
                                            float* As, float* Bs,
                                            int bm, int bn, int kk, int tid)
{
    // A tile 128x32: 1024 16B chunks, 4/thread
#pragma unroll
    for (int i = 0; i < 4; i++) {
        int c = tid + i * 256;
        int r = c >> 3, k4 = (c & 7) << 2;
        cp16(&As[r * LDA + k4], A + (size_t)(bm + r) * GK + kk + k4);
    }
    // B tile 32x128: 1024 16B chunks, 4/thread
#pragma unroll
    for (int i = 0; i < 4; i++) {
        int c = tid + i * 256;
        int r = c >> 5, c4 = (c & 31) << 2;
        cp16(&Bs[r * LDB + c4], B + (size_t)(kk + r) * GN + bn + c4);
    }
}

__device__ __forceinline__ void gemm_core(const float* __restrict__ A,
                                          const float* __restrict__ B,
                                          float* __restrict__ C,
                                          float* sm)
{
    float* As = sm;                          // STAGES x [128][LDA]
    float* Bs = sm + STAGES * ASTAGE;        // STAGES x [BK][LDB]

    const int tid = threadIdx.x;
    const int w   = tid >> 5;
    const int bm  = blockIdx.x * 128;
    const int bn  = blockIdx.y * 128;
    const int wr  = (w >> 1) * 32;
    const int wc  = (w & 1) * 64;

    wmma::fragment<wmma::accumulator, 16, 16, 8, float> acc[2][4];
#pragma unroll
    for (int i = 0; i < 2; i++)
#pragma unroll
        for (int j = 0; j < 4; j++) wmma::fill_fragment(acc[i][j], 0.0f);

    // Prologue: stages 0, 1
    issue_stage(A, B, As, Bs, bm, bn, 0, tid);
    CP_COMMIT();
    issue_stage(A, B, As + ASTAGE, Bs + BSTAGE, bm, bn, BK, tid);
    CP_COMMIT();

    for (int t = 0; t < NT; t++) {
        CP_WAIT1();
        __syncthreads();

        int nk = t + 2;
        if (nk < NT) {
            int buf = nk % STAGES;
            issue_stage(A, B, As + buf * ASTAGE, Bs + buf * BSTAGE, bm, bn, nk * BK, tid);
        }
        CP_COMMIT();   // always commit (empty groups complete instantly)

        const float* Ac = As + (t % STAGES) * ASTAGE;
        const float* Bc = Bs + (t % STAGES) * BSTAGE;
#pragma unroll
        for (int ks = 0; ks < 4; ks++) {
            wmma::fragment<wmma::matrix_a, 16, 16, 8, wmma::precision::tf32, wmma::row_major> a[2];
            wmma::fragment<wmma::matrix_b, 16, 16, 8, wmma::precision::tf32, wmma::row_major> b[4];
#pragma unroll
            for (int i = 0; i < 2; i++)
                wmma::load_matrix_sync(a[i], &Ac[(wr + i * 16) * LDA + ks * 8], LDA);
#pragma unroll
            for (int j = 0; j < 4; j++)
                wmma::load_matrix_sync(b[j], &Bc[(ks * 8) * LDB + wc + j * 16], LDB);
#pragma unroll
            for (int i = 0; i < 2; i++)
#pragma unroll
                for (int j = 0; j < 4; j++)
                    wmma::mma_sync(acc[i][j], a[i], b[j], acc[i][j]);
        }
    }

#pragma unroll
    for (int i = 0; i < 2; i++)
#pragma unroll
        for (int j = 0; j < 4; j++)
            wmma::store_matrix_sync(C + (size_t)(bm + wr + i * 16) * GN + bn + wc + j * 16,
                                    acc[i][j], GN, wmma::mem_row_major);
}

__global__ __launch_bounds__(256, 2) void gemm_qkv(const float* __restrict__ x)
{
    extern __shared__ float sm[];
    const float* B = g_wt + (size_t)blockIdx.z * DIMSZ * DIMSZ;
    float* C = (blockIdx.z == 0) ? g_q : (blockIdx.z == 1) ? g_k : g_v;
    gemm_core(x, B, C, sm);
}

__global__ __launch_bounds__(256, 2) void gemm_out(const float* __restrict__ A,
                                                   float* __restrict__ C)
{
    extern __shared__ float sm[];
    gemm_core(A, g_wt + (size_t)3 * DIMSZ * DIMSZ, C, sm);
}

// ---------------------------------------------------------------------------
// RoPE applied in-place to g_q and g_k.
// ---------------------------------------------------------------------------
__global__ void rope_kernel(const float* __restrict__ fcos, const float* __restrict__ fsin)
{
    int idx = blockIdx.x * blockDim.x + threadIdx.x;  // SEQ*NHEAD*64 pairs
    if (idx >= SEQ * NHEAD * (HDIM / 2)) return;
    int i = idx & 63;
    int h = (idx >> 6) & (NHEAD - 1);
    int s = idx >> 11;
    float c  = fcos[s * 64 + i];
    float sn = fsin[s * 64 + i];
    size_t off = (size_t)s * DIMSZ + h * HDIM + 2 * i;
    float q0 = g_q[off], q1 = g_q[off + 1];
    g_q[off]     = q0 * c - q1 * sn;
    g_q[off + 1] = q0 * sn + q1 * c;
    float k0 = g_k[off], k1 = g_k[off + 1];
    g_k[off]     = k0 * c - k1 * sn;
    g_k[off + 1] = k0 * sn + k1 * c;
}

// ---------------------------------------------------------------------------
// Flash attention: block = (q-block of 64 rows, head). Online softmax, causal.
// ---------------------------------------------------------------------------
#define LDQ 136   // 128 + 8 pad
#define LDS_S 72  // 64 + 8 pad
#define FLASH_SMEM_FLOATS (4 * 64 * LDQ + 64 * LDS_S + 3 * 64)
#define FLASH_SMEM_BYTES (FLASH_SMEM_FLOATS * 4)

__global__ __launch_bounds__(256) void flash_attn()
{
    extern __shared__ float sm[];
    float* Qs   = sm;                  // 64 x LDQ
    float* Ks   = Qs + 64 * LDQ;
    float* Vs   = Ks + 64 * LDQ;
    float* Os   = Vs + 64 * LDQ;
    float* Ss   = Os + 64 * LDQ;       // 64 x LDS_S
    float* mrow = Ss + 64 * LDS_S;
    float* lrow = mrow + 64;
    float* arow = lrow + 64;

    const int qb  = blockIdx.x;
    const int h   = blockIdx.y;
    const int tid = threadIdx.x;
    const int w   = tid >> 5;
    const float scale = 0.08838834764831845f;  // 1/sqrt(128)

    const float* Qg = g_q + (size_t)qb * 64 * DIMSZ + h * HDIM;
#pragma unroll
    for (int i = 0; i < 8; i++) {
        int idx = tid + i * 256;
        int r = idx >> 5, d4 = (idx & 31) << 2;
        float4 v = *reinterpret_cast<const float4*>(Qg + (size_t)r * DIMSZ + d4);
        *reinterpret_cast<float4*>(&Qs[r * LDQ + d4]) =
            make_float4(to_tf32(v.x), to_tf32(v.y), to_tf32(v.z), to_tf32(v.w));
    }
    for (int i = tid; i < 64 * LDQ; i += 256) Os[i] = 0.0f;
    if (tid < 64) { mrow[tid] = -1e30f; lrow[tid] = 0.0f; }
    __syncthreads();

    for (int kt = 0; kt <= qb; kt++) {
        const float* Kg = g_k + (size_t)kt * 64 * DIMSZ + h * HDIM;
        const float* Vg = g_v + (size_t)kt * 64 * DIMSZ + h * HDIM;
#pragma unroll
        for (int i = 0; i < 8; i++) {
            int idx = tid + i * 256;
            int r = idx >> 5, d4 = (idx & 31) << 2;
            float4 kv = *reinterpret_cast<const float4*>(Kg + (size_t)r * DIMSZ + d4);
            float4 vv = *reinterpret_cast<const float4*>(Vg + (size_t)r * DIMSZ + d4);
            *reinterpret_cast<float4*>(&Ks[r * LDQ + d4]) =
                make_float4(to_tf32(kv.x), to_tf32(kv.y), to_tf32(kv.z), to_tf32(kv.w));
            *reinterpret_cast<float4*>(&Vs[r * LDQ + d4]) =
                make_float4(to_tf32(vv.x), to_tf32(vv.y), to_tf32(vv.z), to_tf32(vv.w));
        }
        __syncthreads();

        // S = scale * Q @ K^T : warp grid 4x2, each warp 16x32
        {
            const int wr = (w >> 1) * 16;
            const int wc = (w & 1) * 32;
            wmma::fragment<wmma::accumulator, 16, 16, 8, float> c[2];
            wmma::fill_fragment(c[0], 0.0f);
            wmma::fill_fragment(c[1], 0.0f);
#pragma unroll
            for (int ks = 0; ks < 16; ks++) {
                wmma::fragment<wmma::matrix_a, 16, 16, 8, wmma::precision::tf32, wmma::row_major> a;
                wmma::load_matrix_sync(a, &Qs[wr * LDQ + ks * 8], LDQ);
#pragma unroll
                for (int j = 0; j < 2; j++) {
                    wmma::fragment<wmma::matrix_b, 16, 16, 8, wmma::precision::tf32, wmma::col_major> b;
                    wmma::load_matrix_sync(b, &Ks[(wc + j * 16) * LDQ + ks * 8], LDQ);
                    wmma::mma_sync(c[j], a, b, c[j]);
                }
            }
#pragma unroll
            for (int j = 0; j < 2; j++) {
#pragma unroll
                for (int t = 0; t < c[j].num_elements; t++) c[j].x[t] *= scale;
                wmma::store_matrix_sync(&Ss[wr * LDS_S + wc + j * 16], c[j], LDS_S,
                                        wmma::mem_row_major);
            }
        }
        __syncthreads();

        // Online softmax: 4 threads per row
        {
            int r   = tid >> 2;
            int sub = tid & 3;
            int smax = (kt == qb) ? (r + 1) : 64;
            float mloc = -1e30f;
            int c0 = sub * 16;
#pragma unroll
            for (int c = 0; c < 16; c++) {
                int cc = c0 + c;
                if (cc < smax) mloc = fmaxf(mloc, Ss[r * LDS_S + cc]);
            }
#pragma unroll
            for (int o = 1; o < 4; o <<= 1)
                mloc = fmaxf(mloc, __shfl_xor_sync(0xffffffffu, mloc, o));
            float mo = mrow[r];
            float mn = fmaxf(mo, mloc);
            float alpha = __expf(mo - mn);
            float lsum = 0.0f;
#pragma unroll
            for (int c = 0; c < 16; c++) {
                int cc = c0 + c;
                float p = (cc < smax) ? __expf(Ss[r * LDS_S + cc] - mn) : 0.0f;
                p = to_tf32(p);
                Ss[r * LDS_S + cc] = p;
                lsum += p;
            }
#pragma unroll
            for (int o = 1; o < 4; o <<= 1)
                lsum += __shfl_xor_sync(0xffffffffu, lsum, o);
            if (sub == 0) {
                lrow[r] = lrow[r] * alpha + lsum;
                mrow[r] = mn;
                arow[r] = alpha;
            }
        }
        __syncthreads();

        // Rescale O accumulator
        for (int i = tid; i < 64 * 128; i += 256) {
            int r = i >> 7, d = i & 127;
            Os[r * LDQ + d] *= arow[r];
        }
        __syncthreads();

        // O += P @ V : warp grid 2x4, each warp 32x32
        {
            const int wr = (w >> 2) * 32;
            const int wc = (w & 3) * 32;
            wmma::fragment<wmma::accumulator, 16, 16, 8, float> c[2][2];
#pragma unroll
            for (int i = 0; i < 2; i++)
#pragma unroll
                for (int j = 0; j < 2; j++)
                    wmma::load_matrix_sync(c[i][j], &Os[(wr + i * 16) * LDQ + wc + j * 16],
                                           LDQ, wmma::mem_row_major);
#pragma unroll
            for (int ks = 0; ks < 8; ks++) {
                wmma::fragment<wmma::matrix_a, 16, 16, 8, wmma::precision::tf32, wmma::row_major> a[2];
                wmma::fragment<wmma::matrix_b, 16, 16, 8, wmma::precision::tf32, wmma::row_major> b[2];
#pragma unroll
                for (int i = 0; i < 2; i++)
                    wmma::load_matrix_sync(a[i], &Ss[(wr + i * 16) * LDS_S + ks * 8], LDS_S);
#pragma unroll
                for (int j = 0; j < 2; j++)
                    wmma::load_matrix_sync(b[j], &Vs[(ks * 8) * LDQ + wc + j * 16], LDQ);
#pragma unroll
                for (int i = 0; i < 2; i++)
#pragma unroll
                    for (int j = 0; j < 2; j++)
                        wmma::mma_sync(c[i][j], a[i], b[j], c[i][j]);
            }
#pragma unroll
            for (int i = 0; i < 2; i++)
#pragma unroll
                for (int j = 0; j < 2; j++)
                    wmma::store_matrix_sync(&Os[(wr + i * 16) * LDQ + wc + j * 16],
                                            c[i][j], LDQ, wmma::mem_row_major);
        }
        __syncthreads();
    }

    // Epilogue: normalize and write PRE-ROUNDED to tf32 (so gemm_out's
    // cp.async raw-byte path keeps RN precision).
    float* Og = g_o + (size_t)qb * 64 * DIMSZ + h * HDIM;
    for (int i = tid; i < 64 * 128; i += 256) {
        int r = i >> 7, d = i & 127;
        Og[(size_t)r * DIMSZ + d] = to_tf32(Os[r * LDQ + d] / lrow[r]);
    }
}

// ---------------------------------------------------------------------------
extern "C" void kernel_launch(void* const* d_in, const int* in_sizes, int n_in,
                              void* d_out, int out_size)
{
    const float* x  = (const float*)d_in[0];
    const float* wq = (const float*)d_in[1];
    const float* wk = (const float*)d_in[2];
    const float* wv = (const float*)d_in[3];
    const float* wo = (const float*)d_in[4];
    const float* fc = (const float*)d_in[5];
    const float* fs = (const float*)d_in[6];
    float* out = (float*)d_out;

    float *xt, *wt, *o;
    cudaGetSymbolAddress((void**)&xt, g_xt);
    cudaGetSymbolAddress((void**)&wt, g_wt);
    cudaGetSymbolAddress((void**)&o,  g_o);

    cudaFuncSetAttribute(gemm_qkv, cudaFuncAttributeMaxDynamicSharedMemorySize,
                         GEMM_SMEM_BYTES);
    cudaFuncSetAttribute(gemm_out, cudaFuncAttributeMaxDynamicSharedMemorySize,
                         GEMM_SMEM_BYTES);
    cudaFuncSetAttribute(flash_attn, cudaFuncAttributeMaxDynamicSharedMemorySize,
                         FLASH_SMEM_BYTES);

    // Pre-round inputs to tf32 (RN) so GEMM cp.async path is exact.
    const int W4 = DIMSZ * DIMSZ / 4;       // float4 count per weight
    const int X4 = SEQ * DIMSZ / 4;
    cvt_tf32_kernel<<<(X4 + 255) / 256, 256>>>((const float4*)x, (float4*)xt, X4);
    cvt_tf32_kernel<<<(W4 + 255) / 256, 256>>>((const float4*)wq, (float4*)(wt + (size_t)0 * DIMSZ * DIMSZ), W4);
    cvt_tf32_kernel<<<(W4 + 255) / 256, 256>>>((const float4*)wk, (float4*)(wt + (size_t)1 * DIMSZ * DIMSZ), W4);
    cvt_tf32_kernel<<<(W4 + 255) / 256, 256>>>((const float4*)wv, (float4*)(wt + (size_t)2 * DIMSZ * DIMSZ), W4);
    cvt_tf32_kernel<<<(W4 + 255) / 256, 256>>>((const float4*)wo, (float4*)(wt + (size_t)3 * DIMSZ * DIMSZ), W4);

    dim3 qkv_grid(GM / 128, GN / 128, 3);
    gemm_qkv<<<qkv_grid, 256, GEMM_SMEM_BYTES>>>(xt);

    int npairs = SEQ * NHEAD * (HDIM / 2);
    rope_kernel<<<(npairs + 255) / 256, 256>>>(fc, fs);

    flash_attn<<<dim3(SEQ / 64, NHEAD), 256, FLASH_SMEM_BYTES>>>();

    dim3 ogrid(GM / 128, GN / 128);
    gemm_out<<<ogrid, 256, GEMM_SMEM_BYTES>>>(o, out);
}